// round 5
// baseline (speedup 1.0000x reference)
#include <cuda_runtime.h>

#define N_PIX 32768   // B*H*W
#define EMB   64
#define CH    128
#define NCODE 8192
#define HW    1024    // H*W
#define NBATCH 32

// scratch (no allocations allowed)
__device__ float g_ze[N_PIX * EMB];   // 8 MB
__device__ int   g_ind[N_PIX];
__device__ float g_wn[NCODE];         // 0.5*||w||^2
__device__ float g_loss;

// ---------------------------------------------------------------------------
// K0: codebook half-norms + zero loss accumulator
// ---------------------------------------------------------------------------
__global__ void k_wn(const float* __restrict__ ew) {
    int j = blockIdx.x * blockDim.x + threadIdx.x;  // 8192 threads
    const float4* p = (const float4*)(ew + j * EMB);
    float s = 0.f;
#pragma unroll
    for (int i = 0; i < 16; ++i) {
        float4 v = p[i];
        s += v.x * v.x + v.y * v.y + v.z * v.z + v.w * v.w;
    }
    g_wn[j] = 0.5f * s;
    if (j == 0) g_loss = 0.f;
}

// ---------------------------------------------------------------------------
// K1: z_e[n,e] = sum_c z[b,c,hw] * proj_w[e,c] + proj_b[e]
// block: 256 threads, 16 pixels. grid: 2048.
// ---------------------------------------------------------------------------
__global__ __launch_bounds__(256) void k_proj(const float* __restrict__ z,
                                              const float* __restrict__ pw,
                                              const float* __restrict__ pb) {
    __shared__ float projs[EMB][CH + 4];  // [64][132] row-major, float4-friendly
    __shared__ float zs[CH][18];          // 16 px + pad
    int tid = threadIdx.x;
    int pbase = blockIdx.x * 16;

    // load proj_w (8192 floats) as float4
    for (int i = tid; i < EMB * CH / 4; i += 256) {
        int e = i >> 5;          // 32 float4 per row
        int c4 = (i & 31) << 2;
        float4 v = ((const float4*)pw)[i];
        projs[e][c4 + 0] = v.x;
        projs[e][c4 + 1] = v.y;
        projs[e][c4 + 2] = v.z;
        projs[e][c4 + 3] = v.w;
    }
    // load z tile: 16 pixels x 128 channels (strided gather, coalesced over hw)
    for (int i = tid; i < CH * 16; i += 256) {
        int c = i >> 4;
        int p = i & 15;
        int n = pbase + p;
        zs[c][p] = z[(n >> 10) * (CH * HW) + c * HW + (n & 1023)];
    }
    __syncthreads();

    int e = tid & 63;
    int pg = tid >> 6;
    float bias = pb[e];
    for (int p = pg; p < 16; p += 4) {
        float acc = bias;
#pragma unroll
        for (int c = 0; c < CH; c += 4) {
            float4 w = *(const float4*)&projs[e][c];
            acc += w.x * zs[c][p];
            acc += w.y * zs[c + 1][p];
            acc += w.z * zs[c + 2][p];
            acc += w.w * zs[c + 3][p];
        }
        g_ze[(pbase + p) * EMB + e] = acc;
    }
}

// ---------------------------------------------------------------------------
// K2: argmax over codes of (x.w - 0.5||w||^2), fp32 via packed fma.rn.f32x2
// block: 256 threads (tx 0..15 codes, ty 0..15 queries)
// tile: 128 queries x 128 codes (64 f32x2 pairs), K=64 fully resident
// thread tile: 8 queries x 4 code-pairs (8 codes)
// smem (dynamic): Qs[64][132] + Cs[64][130] + wns[128]  = 67584 B
// ---------------------------------------------------------------------------
#define TQ 128
#define TCODES 128
#define QS_STRIDE 132
#define CS_STRIDE 130

__global__ __launch_bounds__(256, 2) void k_argmax(const float* __restrict__ ew) {
    extern __shared__ float sm[];
    float* Qs  = sm;                        // [64][132]  Qs[k*132 + q]
    float* Cs  = sm + 64 * QS_STRIDE;       // [64][130]  Cs[k*130 + c]
    float* wns = Cs + 64 * CS_STRIDE;       // [128]

    int tid = threadIdx.x;
    int tx = tid & 15;
    int ty = tid >> 4;
    int qb = blockIdx.x * TQ;

    // load Q tile transposed into K-major smem
    for (int i = tid; i < TQ * 16; i += 256) {
        int q = i >> 4;
        int k4 = (i & 15) << 2;
        float4 v = *(const float4*)&g_ze[(qb + q) * EMB + k4];
        Qs[(k4 + 0) * QS_STRIDE + q] = v.x;
        Qs[(k4 + 1) * QS_STRIDE + q] = v.y;
        Qs[(k4 + 2) * QS_STRIDE + q] = v.z;
        Qs[(k4 + 3) * QS_STRIDE + q] = v.w;
    }

    float bestv[8];
    int   besti[8];
#pragma unroll
    for (int i = 0; i < 8; ++i) { bestv[i] = -3.0e38f; besti[i] = 0; }

    unsigned long long acc[8][4];

    for (int t = 0; t < NCODE / TCODES; ++t) {
        int cb = t * TCODES;
        // load C tile transposed (K-major; pairs of adjacent codes contiguous)
        for (int i = tid; i < TCODES * 16; i += 256) {
            int c = i >> 4;
            int k4 = (i & 15) << 2;
            float4 v = *(const float4*)&ew[(cb + c) * EMB + k4];
            Cs[(k4 + 0) * CS_STRIDE + c] = v.x;
            Cs[(k4 + 1) * CS_STRIDE + c] = v.y;
            Cs[(k4 + 2) * CS_STRIDE + c] = v.z;
            Cs[(k4 + 3) * CS_STRIDE + c] = v.w;
        }
        if (tid < TCODES) wns[tid] = g_wn[cb + tid];
        __syncthreads();

#pragma unroll
        for (int i = 0; i < 8; ++i)
#pragma unroll
            for (int j = 0; j < 4; ++j) acc[i][j] = 0ULL;

#pragma unroll 4
        for (int k = 0; k < 64; ++k) {
            const float* Qrow = Qs + k * QS_STRIDE;
            const float* Crow = Cs + k * CS_STRIDE;
            unsigned long long qq[8];
#pragma unroll
            for (int i = 0; i < 8; ++i) {
                float qv = Qrow[ty + 16 * i];
                asm("mov.b64 %0, {%1, %1};" : "=l"(qq[i]) : "f"(qv));
            }
            unsigned long long cv[4];
#pragma unroll
            for (int j = 0; j < 4; ++j)
                cv[j] = *(const unsigned long long*)&Crow[2 * (tx + 16 * j)];
#pragma unroll
            for (int i = 0; i < 8; ++i)
#pragma unroll
                for (int j = 0; j < 4; ++j)
                    asm("fma.rn.f32x2 %0, %1, %2, %0;"
                        : "+l"(acc[i][j]) : "l"(qq[i]), "l"(cv[j]));
        }

        // epilogue: score = dot - 0.5||w||^2 ; strict > keeps lowest index
#pragma unroll
        for (int j = 0; j < 4; ++j) {
            int cloc = 2 * (tx + 16 * j);
            float w0 = wns[cloc], w1 = wns[cloc + 1];
            int cg = cb + cloc;
#pragma unroll
            for (int i = 0; i < 8; ++i) {
                float s0, s1;
                asm("mov.b64 {%0, %1}, %2;" : "=f"(s0), "=f"(s1) : "l"(acc[i][j]));
                float sc0 = s0 - w0;
                float sc1 = s1 - w1;
                if (sc0 > bestv[i]) { bestv[i] = sc0; besti[i] = cg; }
                if (sc1 > bestv[i]) { bestv[i] = sc1; besti[i] = cg + 1; }
            }
        }
        __syncthreads();
    }

    // reduce across the 16 tx lanes (each holds disjoint code subsets per q)
#pragma unroll
    for (int i = 0; i < 8; ++i) {
        float v = bestv[i];
        int idx = besti[i];
#pragma unroll
        for (int off = 8; off > 0; off >>= 1) {
            float ov = __shfl_down_sync(0xffffffffu, v, off, 16);
            int   oi = __shfl_down_sync(0xffffffffu, idx, off, 16);
            if (ov > v || (ov == v && oi < idx)) { v = ov; idx = oi; }
        }
        if (tx == 0) g_ind[qb + ty + 16 * i] = idx;
    }
}

// ---------------------------------------------------------------------------
// K3: gather codebook rows -> out [B,E,H,W] and z_q_flat [N,E]; loss partials;
//     indices as float. block 256 = 4 pixels x 64 emb.
// ---------------------------------------------------------------------------
__global__ __launch_bounds__(256) void k_gather(const float* __restrict__ ew,
                                                float* __restrict__ out,
                                                int full_out) {
    int tid = threadIdx.x;
    int n = blockIdx.x * 4 + (tid >> 6);
    int e = tid & 63;
    int idx = g_ind[n];
    float v = ew[idx * EMB + e];
    float d = v - g_ze[n * EMB + e];
    int b = n >> 10;
    int hw = n & 1023;
    out[b * (EMB * HW) + e * HW + hw] = v;          // out (straight-through == z_q_emb)
    if (full_out) {
        out[N_PIX * EMB + n * EMB + e] = v;         // z_q_flat
        if (e == 0) out[2 * N_PIX * EMB + 1 + n] = (float)idx;  // z_q_ind
    }
    // block-reduce d*d
    float s = d * d;
#pragma unroll
    for (int off = 16; off > 0; off >>= 1)
        s += __shfl_down_sync(0xffffffffu, s, off);
    __shared__ float ps[8];
    if ((tid & 31) == 0) ps[tid >> 5] = s;
    __syncthreads();
    if (tid < 8) {
        s = ps[tid];
#pragma unroll
        for (int off = 4; off > 0; off >>= 1)
            s += __shfl_down_sync(0xffu, s, off);
        if (tid == 0) atomicAdd(&g_loss, s);
    }
}

// ---------------------------------------------------------------------------
// K4: latent_loss = 12.5 * mean(diff^2)
// ---------------------------------------------------------------------------
__global__ void k_fin(float* __restrict__ out, int full_out) {
    if (full_out)
        out[2 * N_PIX * EMB] = 12.5f * g_loss / (float)(N_PIX * EMB);
}

// ---------------------------------------------------------------------------
extern "C" void kernel_launch(void* const* d_in, const int* in_sizes, int n_in,
                              void* d_out, int out_size) {
    const float* z  = (const float*)d_in[0];
    const float* pw = (const float*)d_in[1];
    const float* pb = (const float*)d_in[2];
    const float* ew = (const float*)d_in[3];
    float* out = (float*)d_out;

    int full_out = (out_size >= 2 * N_PIX * EMB + 1 + N_PIX) ? 1 : 0;

    const int smem = (64 * QS_STRIDE + 64 * CS_STRIDE + 128) * 4;  // 67584
    cudaFuncSetAttribute(k_argmax, cudaFuncAttributeMaxDynamicSharedMemorySize, smem);

    k_wn<<<NCODE / 256, 256>>>(ew);
    k_proj<<<N_PIX / 16, 256>>>(z, pw, pb);
    k_argmax<<<N_PIX / TQ, 256, smem>>>(ew);
    k_gather<<<N_PIX / 4, 256>>>(ew, out, full_out);
    k_fin<<<1, 1>>>(out, full_out);
}